// round 7
// baseline (speedup 1.0000x reference)
#include <cuda_runtime.h>
#include <math.h>

#define LAMDA 0.1f
#define T_AVG 8192
#define THREADS 512
#define BLOCKS (148 * 2)
#define NWARPS (THREADS / 32)
// t4 (= T/4 float4) == 4 * THREADS: one unrolled group == the cyclic offset.
#define T4 (T_AVG / 4)

// Accumulators: zero at module load; reset by the last block each launch,
// so every graph replay starts clean. Counter self-wraps via atomicInc.
__device__ float g_acc0;
__device__ float g_acc1;
__device__ unsigned int g_count;

__device__ __forceinline__ float sq4(float4 a, float4 b) {
    float d0 = a.x - b.x;
    float d1 = a.y - b.y;
    float d2 = a.z - b.z;
    float d3 = a.w - b.w;
    return d0 * d0 + d1 * d1 + d2 * d2 + d3 * d3;
}

__global__ void __launch_bounds__(THREADS, 2) fused_loss_kernel(
    const float4* __restrict__ in,
    const float4* __restrict__ tg,
    float* __restrict__ out,
    int n4, int lim4 /* = n4 - T4 */, int chunk,
    float inv_n, int nSteps)
{
    float s_mse = 0.0f;
    float s_cyc = 0.0f;

    const int base = blockIdx.x * chunk;
    const int end = min(base + chunk, n4);
    const int end_cyc = min(end, lim4);
    int i = base + threadIdx.x;   // trailing index

    // ── Register ring: because T4 == 4*THREADS, the c-load of group g
    //    (address i+T4) is exactly the a-value of group g+1 for this thread.
    //    Each group therefore loads only 8 float4 (c + tg) instead of 12.
    if (i + 3 * THREADS < end_cyc) {
        // Prologue: direct-load the first group's a-values.
        float4 r0 = in[i];
        float4 r1 = in[i + THREADS];
        float4 r2 = in[i + 2 * THREADS];
        float4 r3 = in[i + 3 * THREADS];
        for (; i + 3 * THREADS < end_cyc; i += 4 * THREADS) {
            // First half: c0,c1 (future a) + b0,b1
            float4 c0 = in[i + T4];
            float4 c1 = in[i + THREADS + T4];
            float4 b0 = __ldcs(&tg[i]);
            float4 b1 = __ldcs(&tg[i + THREADS]);
            s_mse += sq4(r0, b0);
            s_mse += sq4(r1, b1);
            s_cyc += sq4(r0, c0);
            s_cyc += sq4(r1, c1);
            // Second half: c2,c3 + b2,b3
            float4 c2 = in[i + 2 * THREADS + T4];
            float4 c3 = in[i + 3 * THREADS + T4];
            float4 b2 = __ldcs(&tg[i + 2 * THREADS]);
            float4 b3 = __ldcs(&tg[i + 3 * THREADS]);
            s_mse += sq4(r2, b2);
            s_mse += sq4(r3, b3);
            s_cyc += sq4(r2, c2);
            s_cyc += sq4(r3, c3);
            // Rotate ring: this group's c is next group's a.
            r0 = c0; r1 = c1; r2 = c2; r3 = c3;
        }
        // Ring values for the unprocessed trailing group are discarded;
        // the tail loops below re-load them (L2 hits, negligible).
    }

    // Tail of the cyc region (direct loads).
    for (; i < end_cyc; i += THREADS) {
        float4 a = in[i];
        float4 b = __ldcs(&tg[i]);
        float4 c = in[i + T4];
        s_mse += sq4(a, b);
        s_cyc += sq4(a, c);
    }
    // MSE-only region (last T elements of n; only the final data block).
    for (; i < end; i += THREADS) {
        float4 a = in[i];
        float4 b = __ldcs(&tg[i]);
        s_mse += sq4(a, b);
    }

    // Warp reduction
    #pragma unroll
    for (int off = 16; off > 0; off >>= 1) {
        s_mse += __shfl_xor_sync(0xffffffffu, s_mse, off);
        s_cyc += __shfl_xor_sync(0xffffffffu, s_cyc, off);
    }

    __shared__ float sm_mse[NWARPS];
    __shared__ float sm_cyc[NWARPS];
    int wid = threadIdx.x >> 5;
    int lid = threadIdx.x & 31;
    if (lid == 0) {
        sm_mse[wid] = s_mse;
        sm_cyc[wid] = s_cyc;
    }
    __syncthreads();

    if (threadIdx.x == 0) {
        float bm = sm_mse[0];
        float bc = sm_cyc[0];
        #pragma unroll
        for (int w = 1; w < NWARPS; w++) {
            bm += sm_mse[w];
            bc += sm_cyc[w];
        }
        atomicAdd(&g_acc0, bm);
        atomicAdd(&g_acc1, bc);
        __threadfence();
        // atomicInc wraps to 0 when old == gridDim.x-1 -> self-resetting counter
        unsigned int ticket = atomicInc(&g_count, gridDim.x - 1);
        if (ticket == gridDim.x - 1) {
            float tot_mse = atomicAdd(&g_acc0, 0.0f);
            float tot_cyc = atomicAdd(&g_acc1, 0.0f);
            float l1 = (nSteps != 1) ? (LAMDA * sqrtf(tot_cyc)) : 0.0f;
            out[0] = tot_mse * inv_n + l1;
            // Reset for next graph replay.
            g_acc0 = 0.0f;
            g_acc1 = 0.0f;
        }
    }
}

extern "C" void kernel_launch(void* const* d_in, const int* in_sizes, int n_in,
                              void* d_out, int out_size) {
    const float* input  = (const float*)d_in[0];
    const float* target = (const float*)d_in[1];
    float* out = (float*)d_out;

    int n = in_sizes[0];         // 16,777,216
    int n4 = n / 4;
    int T = T_AVG;               // 8192 (fixed for this problem)
    int nSteps = n / T;          // 2048
    int lim4 = n4 - T4;          // (N-1)*T / 4

    // Contiguous per-block chunk, rounded up to a full unrolled group
    // (4*THREADS) so full blocks run only the ring path.
    int grp = 4 * THREADS;
    int chunk = (n4 + BLOCKS - 1) / BLOCKS;
    chunk = (chunk + grp - 1) / grp * grp;

    fused_loss_kernel<<<BLOCKS, THREADS>>>(
        (const float4*)input, (const float4*)target, out,
        n4, lim4, chunk, 1.0f / (float)n, nSteps);
}